// round 1
// baseline (speedup 1.0000x reference)
#include <cuda_runtime.h>
#include <cstdint>

#define NMAX 100000
#define D 64

__device__ float g_m[(size_t)NMAX * D];
__device__ float g_agg[(size_t)NMAX * D];
__device__ float g_deg[NMAX];

__device__ __forceinline__ void red_add_v4(float* addr, float4 v) {
    asm volatile("red.global.add.v4.f32 [%0], {%1, %2, %3, %4};"
                 :: "l"(addr), "f"(v.x), "f"(v.y), "f"(v.z), "f"(v.w) : "memory");
}
__device__ __forceinline__ void red_add_f32(float* addr, float v) {
    asm volatile("red.global.add.f32 [%0], %1;" :: "l"(addr), "f"(v) : "memory");
}

// --------------------------------------------------------------------------
// Zero the aggregation scratch (agg + deg)
// --------------------------------------------------------------------------
__global__ void zero_kernel(int n) {
    int stride = gridDim.x * blockDim.x;
    int tid = blockIdx.x * blockDim.x + threadIdx.x;
    int total4 = n * (D / 4);
    float4 z = make_float4(0.f, 0.f, 0.f, 0.f);
    for (int i = tid; i < total4; i += stride)
        reinterpret_cast<float4*>(g_agg)[i] = z;
    for (int i = tid; i < n; i += stride)
        g_deg[i] = 0.f;
}

// --------------------------------------------------------------------------
// Per-node message MLP: m = relu(x @ W_msg + b_msg)   [N, 64]
// Warp per node; lane j holds output cols j and j+32.
// --------------------------------------------------------------------------
__global__ void __launch_bounds__(256) msg_kernel(
    const float* __restrict__ x, const float* __restrict__ W,
    const float* __restrict__ b, int n)
{
    __shared__ float2 Ws[D][32];   // Ws[k][j] = (W[k][j], W[k][j+32])
    __shared__ float  bs[D];
    __shared__ float  xs[8][D];

    int tid = threadIdx.x;
    for (int i = tid; i < D * 32; i += blockDim.x) {
        int k = i >> 5, j = i & 31;
        Ws[k][j] = make_float2(W[k * D + j], W[k * D + j + 32]);
    }
    for (int i = tid; i < D; i += blockDim.x) bs[i] = b[i];
    __syncthreads();

    int warp = tid >> 5, lane = tid & 31;
    int gw = blockIdx.x * 8 + warp;
    int nw = gridDim.x * 8;
    for (int node = gw; node < n; node += nw) {
        const float* xr = x + (size_t)node * D;
        xs[warp][lane]      = xr[lane];
        xs[warp][lane + 32] = xr[lane + 32];
        __syncwarp();
        float a0 = bs[lane], a1 = bs[lane + 32];
#pragma unroll
        for (int k4 = 0; k4 < D / 4; k4++) {
            float4 xv = *reinterpret_cast<const float4*>(&xs[warp][k4 * 4]);
            float2 w;
            w = Ws[4 * k4 + 0][lane]; a0 = fmaf(xv.x, w.x, a0); a1 = fmaf(xv.x, w.y, a1);
            w = Ws[4 * k4 + 1][lane]; a0 = fmaf(xv.y, w.x, a0); a1 = fmaf(xv.y, w.y, a1);
            w = Ws[4 * k4 + 2][lane]; a0 = fmaf(xv.z, w.x, a0); a1 = fmaf(xv.z, w.y, a1);
            w = Ws[4 * k4 + 3][lane]; a0 = fmaf(xv.w, w.x, a0); a1 = fmaf(xv.w, w.y, a1);
        }
        a0 = fmaxf(a0, 0.f);
        a1 = fmaxf(a1, 0.f);
        float* mr = g_m + (size_t)node * D;
        mr[lane]      = a0;
        mr[lane + 32] = a1;
        __syncwarp();
    }
}

// --------------------------------------------------------------------------
// Edge scatter: agg[dst] += m[src] * w_e ; deg[dst] += 1
// 16 threads per edge, each handles one float4 via L2-side vector reduction.
// --------------------------------------------------------------------------
__global__ void __launch_bounds__(256) edge_kernel(
    const int* __restrict__ ei, const float* __restrict__ ew, int E)
{
    int t = blockIdx.x * blockDim.x + threadIdx.x;
    int e   = t >> 4;
    int sub = t & 15;
    if (e >= E) return;
    int   src = __ldg(ei + e);
    int   dst = __ldg(ei + E + e);
    float w   = __ldg(ew + e);

    const float4 mv = *reinterpret_cast<const float4*>(g_m + (size_t)src * D + sub * 4);
    float4 v = make_float4(mv.x * w, mv.y * w, mv.z * w, mv.w * w);
    red_add_v4(g_agg + (size_t)dst * D + sub * 4, v);
    if (sub == 0) red_add_f32(g_deg + dst, 1.0f);
}

// --------------------------------------------------------------------------
// Update: h = relu([x || agg/max(deg,1)] @ W_upd + b_upd); out = h / max(||h||,1e-12)
// Warp per node; K = 128.
// --------------------------------------------------------------------------
__global__ void __launch_bounds__(256) upd_kernel(
    const float* __restrict__ x, const float* __restrict__ W,
    const float* __restrict__ b, float* __restrict__ out, int n)
{
    __shared__ float2 Ws[2 * D][32];   // 32 KB
    __shared__ float  bs[D];
    __shared__ float  xs[8][2 * D];    // 4 KB

    int tid = threadIdx.x;
    for (int i = tid; i < 2 * D * 32; i += blockDim.x) {
        int k = i >> 5, j = i & 31;
        Ws[k][j] = make_float2(W[k * D + j], W[k * D + j + 32]);
    }
    for (int i = tid; i < D; i += blockDim.x) bs[i] = b[i];
    __syncthreads();

    int warp = tid >> 5, lane = tid & 31;
    int gw = blockIdx.x * 8 + warp;
    int nw = gridDim.x * 8;
    for (int node = gw; node < n; node += nw) {
        const float* xr = x + (size_t)node * D;
        const float* ar = g_agg + (size_t)node * D;
        float inv_deg = 1.0f / fmaxf(g_deg[node], 1.0f);
        xs[warp][lane]           = xr[lane];
        xs[warp][lane + 32]      = xr[lane + 32];
        xs[warp][D + lane]       = ar[lane]      * inv_deg;
        xs[warp][D + lane + 32]  = ar[lane + 32] * inv_deg;
        __syncwarp();

        float a0 = bs[lane], a1 = bs[lane + 32];
#pragma unroll
        for (int k4 = 0; k4 < (2 * D) / 4; k4++) {
            float4 xv = *reinterpret_cast<const float4*>(&xs[warp][k4 * 4]);
            float2 w;
            w = Ws[4 * k4 + 0][lane]; a0 = fmaf(xv.x, w.x, a0); a1 = fmaf(xv.x, w.y, a1);
            w = Ws[4 * k4 + 1][lane]; a0 = fmaf(xv.y, w.x, a0); a1 = fmaf(xv.y, w.y, a1);
            w = Ws[4 * k4 + 2][lane]; a0 = fmaf(xv.z, w.x, a0); a1 = fmaf(xv.z, w.y, a1);
            w = Ws[4 * k4 + 3][lane]; a0 = fmaf(xv.w, w.x, a0); a1 = fmaf(xv.w, w.y, a1);
        }
        a0 = fmaxf(a0, 0.f);
        a1 = fmaxf(a1, 0.f);

        // Row L2 norm across the warp
        float ss = a0 * a0 + a1 * a1;
#pragma unroll
        for (int off = 16; off > 0; off >>= 1)
            ss += __shfl_xor_sync(0xFFFFFFFF, ss, off);
        float inv_norm = 1.0f / fmaxf(sqrtf(ss), 1e-12f);

        float* orow = out + (size_t)node * D;
        orow[lane]      = a0 * inv_norm;
        orow[lane + 32] = a1 * inv_norm;
        __syncwarp();
    }
}

// --------------------------------------------------------------------------
extern "C" void kernel_launch(void* const* d_in, const int* in_sizes, int n_in,
                              void* d_out, int out_size)
{
    const float* x  = (const float*)d_in[0];
    const int*   ei = (const int*)  d_in[1];
    const float* ew = (const float*)d_in[2];
    const float* Wm = (const float*)d_in[3];
    const float* bm = (const float*)d_in[4];
    const float* Wu = (const float*)d_in[5];
    const float* bu = (const float*)d_in[6];
    float* out = (float*)d_out;

    int n = in_sizes[0] / D;       // 100000
    int E = in_sizes[1] / 2;       // 1200000
    if (n > NMAX) n = NMAX;

    zero_kernel<<<2048, 256>>>(n);
    msg_kernel<<<592, 256>>>(x, Wm, bm, n);
    int edge_threads = E * 16;
    edge_kernel<<<(edge_threads + 255) / 256, 256>>>(ei, ew, E);
    upd_kernel<<<592, 256>>>(x, Wu, bu, out, n);
}

// round 2
// speedup vs baseline: 1.4470x; 1.4470x over previous
#include <cuda_runtime.h>
#include <cstdint>

#define NMAX 100000
#define D 64
#define NB 4

__device__ float g_m[(size_t)NMAX * D];
__device__ float g_agg[(size_t)NMAX * D];
__device__ float g_deg[NMAX];

__device__ __forceinline__ void red_add_v4(float* addr, float4 v) {
    asm volatile("red.global.add.v4.f32 [%0], {%1, %2, %3, %4};"
                 :: "l"(addr), "f"(v.x), "f"(v.y), "f"(v.z), "f"(v.w) : "memory");
}
__device__ __forceinline__ void red_add_f32(float* addr, float v) {
    asm volatile("red.global.add.f32 [%0], %1;" :: "l"(addr), "f"(v) : "memory");
}

// --------------------------------------------------------------------------
// Zero the aggregation scratch (agg + deg)
// --------------------------------------------------------------------------
__global__ void zero_kernel(int n) {
    int stride = gridDim.x * blockDim.x;
    int tid = blockIdx.x * blockDim.x + threadIdx.x;
    int total4 = n * (D / 4);
    float4 z = make_float4(0.f, 0.f, 0.f, 0.f);
    for (int i = tid; i < total4; i += stride)
        reinterpret_cast<float4*>(g_agg)[i] = z;
    for (int i = tid; i < n; i += stride)
        g_deg[i] = 0.f;
}

// --------------------------------------------------------------------------
// Per-node message MLP: m = relu(x @ W_msg + b_msg)   [N, 64]
// Warp computes NB=4 nodes at once; lane j holds output cols j and j+32.
// Weights packed: Wp[k2][j] = (W[2k2][j], W[2k2][j+32], W[2k2+1][j], W[2k2+1][j+32])
// --------------------------------------------------------------------------
__global__ void __launch_bounds__(256) msg_kernel(
    const float* __restrict__ x, const float* __restrict__ W,
    const float* __restrict__ b, int n)
{
    __shared__ float4 Wp[D / 2][32];        // 16 KB
    __shared__ float4 xs[8][NB][D / 4];     // 8 KB

    int tid = threadIdx.x;
    for (int i = tid; i < (D / 2) * 32; i += blockDim.x) {
        int k2 = i >> 5, j = i & 31;
        Wp[k2][j] = make_float4(W[(2 * k2) * D + j],     W[(2 * k2) * D + j + 32],
                                W[(2 * k2 + 1) * D + j], W[(2 * k2 + 1) * D + j + 32]);
    }
    __syncthreads();

    int warp = tid >> 5, lane = tid & 31;
    float b0 = b[lane], b1 = b[lane + 32];
    int gw = blockIdx.x * 8 + warp;
    int nwp = gridDim.x * 8;

    for (int base = gw * NB; base < n; base += nwp * NB) {
        int cnt = min(NB, n - base);
#pragma unroll
        for (int nb = 0; nb < NB; nb++) {
            if (nb < cnt && lane < D / 4)
                xs[warp][nb][lane] =
                    reinterpret_cast<const float4*>(x)[(size_t)(base + nb) * (D / 4) + lane];
        }
        __syncwarp();

        float a0[NB], a1[NB];
#pragma unroll
        for (int nb = 0; nb < NB; nb++) { a0[nb] = b0; a1[nb] = b1; }

#pragma unroll
        for (int k4 = 0; k4 < D / 4; k4++) {
            float4 wA = Wp[2 * k4][lane];
            float4 wB = Wp[2 * k4 + 1][lane];
#pragma unroll
            for (int nb = 0; nb < NB; nb++) {
                float4 xv = xs[warp][nb][k4];
                a0[nb] = fmaf(xv.x, wA.x, a0[nb]); a1[nb] = fmaf(xv.x, wA.y, a1[nb]);
                a0[nb] = fmaf(xv.y, wA.z, a0[nb]); a1[nb] = fmaf(xv.y, wA.w, a1[nb]);
                a0[nb] = fmaf(xv.z, wB.x, a0[nb]); a1[nb] = fmaf(xv.z, wB.y, a1[nb]);
                a0[nb] = fmaf(xv.w, wB.z, a0[nb]); a1[nb] = fmaf(xv.w, wB.w, a1[nb]);
            }
        }

#pragma unroll
        for (int nb = 0; nb < NB; nb++) {
            if (nb < cnt) {
                float* mr = g_m + (size_t)(base + nb) * D;
                mr[lane]      = fmaxf(a0[nb], 0.f);
                mr[lane + 32] = fmaxf(a1[nb], 0.f);
            }
        }
        __syncwarp();
    }
}

// --------------------------------------------------------------------------
// Edge scatter: agg[dst] += m[src] * w_e ; deg[dst] += 1
// 16 threads per edge, each handles one float4 via L2-side vector reduction.
// --------------------------------------------------------------------------
__global__ void __launch_bounds__(256) edge_kernel(
    const int* __restrict__ ei, const float* __restrict__ ew, int E)
{
    int t = blockIdx.x * blockDim.x + threadIdx.x;
    int e   = t >> 4;
    int sub = t & 15;
    if (e >= E) return;
    int   src = __ldg(ei + e);
    int   dst = __ldg(ei + E + e);
    float w   = __ldg(ew + e);

    const float4 mv = *reinterpret_cast<const float4*>(g_m + (size_t)src * D + sub * 4);
    float4 v = make_float4(mv.x * w, mv.y * w, mv.z * w, mv.w * w);
    red_add_v4(g_agg + (size_t)dst * D + sub * 4, v);
    if (sub == 0) red_add_f32(g_deg + dst, 1.0f);
}

// --------------------------------------------------------------------------
// Update: h = relu([x || agg/max(deg,1)] @ W_upd + b_upd); out = h / max(||h||,1e-12)
// Warp computes NB=4 nodes; K = 128. 4 warps/block (smem: 32KB W + 8KB x).
// --------------------------------------------------------------------------
__global__ void __launch_bounds__(128) upd_kernel(
    const float* __restrict__ x, const float* __restrict__ W,
    const float* __restrict__ b, float* __restrict__ out, int n)
{
    __shared__ float4 Wp[D][32];             // 32 KB  (2D/2 = 64 rows)
    __shared__ float4 xs[4][NB][2 * D / 4];  // 8 KB

    int tid = threadIdx.x;
    for (int i = tid; i < D * 32; i += blockDim.x) {
        int k2 = i >> 5, j = i & 31;
        Wp[k2][j] = make_float4(W[(2 * k2) * D + j],     W[(2 * k2) * D + j + 32],
                                W[(2 * k2 + 1) * D + j], W[(2 * k2 + 1) * D + j + 32]);
    }
    __syncthreads();

    int warp = tid >> 5, lane = tid & 31;
    float b0 = b[lane], b1 = b[lane + 32];
    int gw = blockIdx.x * 4 + warp;
    int nwp = gridDim.x * 4;

    for (int base = gw * NB; base < n; base += nwp * NB) {
        int cnt = min(NB, n - base);
#pragma unroll
        for (int nb = 0; nb < NB; nb++) {
            if (nb < cnt) {
                int node = base + nb;
                float4 v;
                if (lane < 16) {
                    v = reinterpret_cast<const float4*>(x)[(size_t)node * 16 + lane];
                } else {
                    float invd = 1.0f / fmaxf(g_deg[node], 1.0f);
                    float4 a = reinterpret_cast<const float4*>(g_agg)[(size_t)node * 16 + (lane - 16)];
                    v = make_float4(a.x * invd, a.y * invd, a.z * invd, a.w * invd);
                }
                xs[warp][nb][lane] = v;
            }
        }
        __syncwarp();

        float a0[NB], a1[NB];
#pragma unroll
        for (int nb = 0; nb < NB; nb++) { a0[nb] = b0; a1[nb] = b1; }

#pragma unroll
        for (int k4 = 0; k4 < (2 * D) / 4; k4++) {
            float4 wA = Wp[2 * k4][lane];
            float4 wB = Wp[2 * k4 + 1][lane];
#pragma unroll
            for (int nb = 0; nb < NB; nb++) {
                float4 xv = xs[warp][nb][k4];
                a0[nb] = fmaf(xv.x, wA.x, a0[nb]); a1[nb] = fmaf(xv.x, wA.y, a1[nb]);
                a0[nb] = fmaf(xv.y, wA.z, a0[nb]); a1[nb] = fmaf(xv.y, wA.w, a1[nb]);
                a0[nb] = fmaf(xv.z, wB.x, a0[nb]); a1[nb] = fmaf(xv.z, wB.y, a1[nb]);
                a0[nb] = fmaf(xv.w, wB.z, a0[nb]); a1[nb] = fmaf(xv.w, wB.w, a1[nb]);
            }
        }

#pragma unroll
        for (int nb = 0; nb < NB; nb++) {
            if (nb < cnt) {
                float h0 = fmaxf(a0[nb], 0.f);
                float h1 = fmaxf(a1[nb], 0.f);
                float ss = h0 * h0 + h1 * h1;
#pragma unroll
                for (int off = 16; off > 0; off >>= 1)
                    ss += __shfl_xor_sync(0xFFFFFFFF, ss, off);
                float inv = 1.0f / fmaxf(sqrtf(ss), 1e-12f);
                float* orow = out + (size_t)(base + nb) * D;
                orow[lane]      = h0 * inv;
                orow[lane + 32] = h1 * inv;
            }
        }
        __syncwarp();
    }
}

// --------------------------------------------------------------------------
extern "C" void kernel_launch(void* const* d_in, const int* in_sizes, int n_in,
                              void* d_out, int out_size)
{
    const float* x  = (const float*)d_in[0];
    const int*   ei = (const int*)  d_in[1];
    const float* ew = (const float*)d_in[2];
    const float* Wm = (const float*)d_in[3];
    const float* bm = (const float*)d_in[4];
    const float* Wu = (const float*)d_in[5];
    const float* bu = (const float*)d_in[6];
    float* out = (float*)d_out;

    int n = in_sizes[0] / D;       // 100000
    int E = in_sizes[1] / 2;       // 1200000
    if (n > NMAX) n = NMAX;

    zero_kernel<<<1024, 256>>>(n);
    msg_kernel<<<1184, 256>>>(x, Wm, bm, n);
    int edge_threads = E * 16;
    edge_kernel<<<(edge_threads + 255) / 256, 256>>>(ei, ew, E);
    upd_kernel<<<740, 128>>>(x, Wu, bu, out, n);
}